// round 11
// baseline (speedup 1.0000x reference)
#include <cuda_runtime.h>
#include <math.h>
#include <stdint.h>

#define NJ 34
#define NV 500000
#define NB 32
#define NQF (NV * 3 / 4)       // 375000 output float4s per batch plane
#define BLK 128
#define NBLOCKS ((NV + BLK - 1) / BLK)   // 3907
#define F4_PER_BLK (BLK * 3 / 4)         // 96 float4s per plane per block
#define W_BYTES (BLK * NJ * 4)           // 17408 bytes of weights per block

__constant__ int c_parents[NJ] = {
    -1, 0, 1, 2, 2, 4, 5, 6, 7, 8, 9, 7, 11, 12, 7, 14, 15, 2,
    17, 18, 19, 20, 21, 22, 20, 24, 25, 20, 27, 28, 0, 30, 0, 32
};

__global__ __launch_bounds__(BLK) void fused_lbs_kernel(
    const float* __restrict__ pose,
    const float* __restrict__ joints,
    const float* __restrict__ weights,
    const float* __restrict__ v_template,
    const float* __restrict__ local_adjust,
    const float* __restrict__ disp,
    const float* __restrict__ scale,
    const float* __restrict__ est,
    float4* __restrict__ out)
{
    __shared__ __align__(16) float sA[NJ * 12];        // scaled 3x4 affines
    __shared__ __align__(16) float4 sRot[3 * NB];      // rotated addend table
    __shared__ __align__(16) float sW[BLK * NJ];       // 17 KB weights (TMA dst)
    __shared__ __align__(16) float sVP[BLK * 3];       // posed verts
    __shared__ __align__(16) float sPrep[512];         // phase-0 scratch
    __shared__ __align__(8) uint64_t sMbar;

    float* sT = sPrep;            // NJ*12 = 408 floats
    float* sJ = sPrep + 408;      // NJ*3 = 102 floats

    const int t = threadIdx.x;
    const int w = t >> 5;
    const int l = t & 31;
    const int block_base = blockIdx.x * BLK;

    uint32_t mbar_addr, sw_addr;
    asm("{ .reg .u64 tmp; cvta.to.shared.u64 tmp, %1; cvt.u32.u64 %0, tmp; }"
        : "=r"(mbar_addr) : "l"(&sMbar));
    asm("{ .reg .u64 tmp; cvta.to.shared.u64 tmp, %1; cvt.u32.u64 %0, tmp; }"
        : "=r"(sw_addr) : "l"(sW));

    // ---- init mbarrier, then launch the weight TMA immediately ----
    if (t == 0) {
        asm volatile("mbarrier.init.shared.b64 [%0], %1;"
                     :: "r"(mbar_addr), "r"(1u) : "memory");
    }
    __syncthreads();
    if (t == 0) {
        int nvert = NV - block_base;
        if (nvert > BLK) nvert = BLK;
        uint32_t bytes = (uint32_t)nvert * NJ * 4;     // multiple of 16
        const char* gsrc = (const char*)weights + (size_t)block_base * NJ * 4;
        asm volatile("mbarrier.arrive.expect_tx.shared.b64 _, [%0], %1;"
                     :: "r"(mbar_addr), "r"(bytes) : "memory");
        asm volatile(
            "cp.async.bulk.shared::cta.global.mbarrier::complete_tx::bytes "
            "[%0], [%1], %2, [%3];"
            :: "r"(sw_addr), "l"(gsrc), "r"(bytes), "r"(mbar_addr) : "memory");
    }

    // ---- phase 0a: rotated base table + joints (overlaps TMA) ----
    if (t < 3 * NB) {
        int m = t >> 5;
        int p = t & 31;
        float b0 = disp[0] + est[p * 3 + 0];
        float b1 = disp[1] + est[p * 3 + 1];
        float b2 = disp[2] + est[p * 3 + 2];
        float r0 = (m == 0) ? b0 : ((m == 1) ? b1 : b2);
        float r1 = (m == 0) ? b1 : ((m == 1) ? b2 : b0);
        float r2 = (m == 0) ? b2 : ((m == 1) ? b0 : b1);
        sRot[m * NB + p] = make_float4(r0, r1, r2, r0);
    }
    if (t < NJ * 3) sJ[t] = joints[t];
    __syncthreads();

    // ---- phase 0b: local transforms ----
    if (t < NJ) {
        float rx = pose[t * 3 + 0], ry = pose[t * 3 + 1], rz = pose[t * 3 + 2];
        float ang = sqrtf(rx * rx + ry * ry + rz * rz + 1e-8f);
        float inv = 1.0f / ang;
        float x = rx * inv, y = ry * inv, z = rz * inv;
        float s = sinf(ang), c = cosf(ang), oc = 1.0f - c;
        int p = c_parents[t];
        float tx = sJ[t * 3 + 0], ty = sJ[t * 3 + 1], tz = sJ[t * 3 + 2];
        if (p >= 0) { tx -= sJ[p * 3 + 0]; ty -= sJ[p * 3 + 1]; tz -= sJ[p * 3 + 2]; }
        float* T = sT + t * 12;
        T[0] = c + oc * x * x;      T[1] = oc * x * y - s * z;  T[2]  = oc * x * z + s * y;  T[3]  = tx;
        T[4] = oc * x * y + s * z;  T[5] = c + oc * y * y;      T[6]  = oc * y * z - s * x;  T[7]  = ty;
        T[8] = oc * x * z - s * y;  T[9] = oc * y * z + s * x;  T[10] = c + oc * z * z;      T[11] = tz;
    }
    __syncthreads();

    // ---- phase 0c: ancestor-chain composition -> A (scale folded) ----
    if (t < NJ) {
        int chain[16];
        int d = 0;
        for (int n = t; n >= 0; n = c_parents[n]) chain[d++] = n;
        float G[12];
        const float* Tr = sT + chain[d - 1] * 12;
        #pragma unroll
        for (int k = 0; k < 12; k++) G[k] = Tr[k];
        for (int k = d - 2; k >= 0; k--) {
            const float* Tc = sT + chain[k] * 12;
            float C[12];
            #pragma unroll
            for (int r = 0; r < 3; r++) {
                float g0 = G[r * 4 + 0], g1 = G[r * 4 + 1], g2 = G[r * 4 + 2], g3 = G[r * 4 + 3];
                C[r * 4 + 0] = g0 * Tc[0] + g1 * Tc[4] + g2 * Tc[8];
                C[r * 4 + 1] = g0 * Tc[1] + g1 * Tc[5] + g2 * Tc[9];
                C[r * 4 + 2] = g0 * Tc[2] + g1 * Tc[6] + g2 * Tc[10];
                C[r * 4 + 3] = g0 * Tc[3] + g1 * Tc[7] + g2 * Tc[11] + g3;
            }
            #pragma unroll
            for (int k2 = 0; k2 < 12; k2++) G[k2] = C[k2];
        }
        float sc = scale[0];
        float jx = sJ[t * 3 + 0], jy = sJ[t * 3 + 1], jz = sJ[t * 3 + 2];
        #pragma unroll
        for (int r = 0; r < 3; r++) {
            float tr = G[r * 4 + 0] * jx + G[r * 4 + 1] * jy + G[r * 4 + 2] * jz;
            sA[t * 12 + r * 4 + 0] = sc * G[r * 4 + 0];
            sA[t * 12 + r * 4 + 1] = sc * G[r * 4 + 1];
            sA[t * 12 + r * 4 + 2] = sc * G[r * 4 + 2];
            sA[t * 12 + r * 4 + 3] = sc * (G[r * 4 + 3] - tr);
        }
    }
    __syncthreads();

    // ---- issue vt/la loads early, then wait for the weight TMA ----
    const int v = block_base + t;
    float vtx = 0.f, vty = 0.f, vtz = 0.f, lax = 0.f, lay = 0.f, laz = 0.f;
    if (v < NV) {
        const float* vtp = v_template + (size_t)v * 3;
        const float* lap = local_adjust + (size_t)v * 3;
        vtx = __ldcs(vtp + 0); vty = __ldcs(vtp + 1); vtz = __ldcs(vtp + 2);
        lax = __ldcs(lap + 0); lay = __ldcs(lap + 1); laz = __ldcs(lap + 2);
    }

    {   // mbarrier wait, parity 0
        uint32_t done;
        asm volatile(
            "{\n\t"
            ".reg .pred p;\n\t"
            "mbarrier.try_wait.parity.acquire.cta.shared::cta.b64 p, [%1], %2;\n\t"
            "selp.b32 %0, 1, 0, p;\n\t"
            "}"
            : "=r"(done) : "r"(mbar_addr), "r"(0u) : "memory");
        if (!done) {
            asm volatile(
                "{\n\t"
                ".reg .pred P1;\n\t"
                "WAIT_LOOP_%=:\n\t"
                "mbarrier.try_wait.parity.acquire.cta.shared::cta.b64 P1, [%0], %1, 0x989680;\n\t"
                "@P1 bra.uni WAIT_DONE_%=;\n\t"
                "bra.uni WAIT_LOOP_%=;\n\t"
                "WAIT_DONE_%=:\n\t"
                "}"
                :: "r"(mbar_addr), "r"(0u) : "memory");
        }
    }

    // ---- skin (R5 math; weights now row-major per thread in sW) ----
    float vp0 = 0.0f, vp1 = 0.0f, vp2 = 0.0f;
    if (v < NV) {
        float T[12];
        #pragma unroll
        for (int k = 0; k < 12; k++) T[k] = 0.0f;

        const float2* wp = (const float2*)(sW + t * NJ);
        #pragma unroll
        for (int k = 0; k < 17; k++) {
            float2 w2 = wp[k];
            {
                const float* Aj = sA + (2 * k) * 12;
                float a[12];
                *(float4*)(a + 0) = *(const float4*)(Aj + 0);
                *(float4*)(a + 4) = *(const float4*)(Aj + 4);
                *(float4*)(a + 8) = *(const float4*)(Aj + 8);
                #pragma unroll
                for (int q = 0; q < 12; q++) T[q] += w2.x * a[q];
            }
            {
                const float* Aj = sA + (2 * k + 1) * 12;
                float a[12];
                *(float4*)(a + 0) = *(const float4*)(Aj + 0);
                *(float4*)(a + 4) = *(const float4*)(Aj + 4);
                *(float4*)(a + 8) = *(const float4*)(Aj + 8);
                #pragma unroll
                for (int q = 0; q < 12; q++) T[q] += w2.y * a[q];
            }
        }

        float vx = vtx + lax, vy = vty + lay, vz = vtz + laz;
        vp0 = T[0] * vx + T[1] * vy + T[2]  * vz + T[3];
        vp1 = T[4] * vx + T[5] * vy + T[6]  * vz + T[7];
        vp2 = T[8] * vx + T[9] * vy + T[10] * vz + T[11];
    }

    // ---- stage + balanced stores: all 4 warps, 8 planes each ----
    __syncthreads();
    sVP[t * 3 + 0] = vp0;
    sVP[t * 3 + 1] = vp1;
    sVP[t * 3 + 2] = vp2;
    __syncthreads();

    const int block_f4 = blockIdx.x * F4_PER_BLK;    // multiple of 3
    const float4* sVP4 = (const float4*)sVP;
    const int lm = l % 3;

    #pragma unroll
    for (int i = 0; i < 3; i++) {
        int r = i * 32 + l;
        if (block_f4 + r < NQF) {
            float4 pv = sVP4[r];
            int m = lm + ((i * 32) % 3);             // (i*32)%3 compile-time
            if (m >= 3) m -= 3;
            const float4* rot = sRot + m * NB;
            #pragma unroll
            for (int k = 0; k < 8; k++) {
                int p = w + 4 * k;
                float4 a = rot[p];
                float4 o;
                o.x = pv.x + a.x; o.y = pv.y + a.y; o.z = pv.z + a.z; o.w = pv.w + a.w;
                __stcs(out + (size_t)p * NQF + block_f4 + r, o);
            }
        }
    }
}

// ---------------------------------------------------------------------------
extern "C" void kernel_launch(void* const* d_in, const int* in_sizes, int n_in,
                              void* d_out, int out_size)
{
    const float* pose         = (const float*)d_in[0]; // (34,3)
    const float* joints       = (const float*)d_in[1]; // (34,3)
    const float* weights      = (const float*)d_in[2]; // (V,34)
    const float* v_template   = (const float*)d_in[3]; // (V,3)
    const float* local_adjust = (const float*)d_in[4]; // (V,3)
    const float* displacement = (const float*)d_in[5]; // (1,3)
    const float* scale        = (const float*)d_in[6]; // (1,)
    const float* est          = (const float*)d_in[7]; // (B,3)
    float* out = (float*)d_out;
    (void)in_sizes; (void)n_in; (void)out_size;

    fused_lbs_kernel<<<NBLOCKS, BLK>>>(pose, joints, weights, v_template,
                                       local_adjust, displacement, scale, est,
                                       (float4*)out);
}